// round 6
// baseline (speedup 1.0000x reference)
#include <cuda_runtime.h>
#include <cstdint>

#define MAXN 50000
#define DD 128
#define MAXE 800000
#define LL 4
#define SCAN_B 1024

// Scratch (no allocations allowed)
__device__ int    g_deg[MAXN];
__device__ int    g_fill[MAXN];
__device__ int    g_rowptr[MAXN + 1];
__device__ int    g_bsum[64];
__device__ int    g_boff[64];
__device__ int    g_csr_src[MAXE];
__device__ float  g_dinv[MAXN];
__device__ float  g_h[(size_t)MAXN * DD];          // h' = (X@W)*dinv[row]
__device__ float2 g_x2[(size_t)MAXN * DD];         // layer input, (hi,lo) tf32 pairs
__device__ float2 g_w2[(size_t)LL * DD * DD];      // pre-split W, (hi,lo) pairs

// ---------------- preprocessing ----------------

__global__ void zero_counters_kernel(int n) {
    int i = blockIdx.x * blockDim.x + threadIdx.x;
    if (i < n) { g_deg[i] = 0; g_fill[i] = 0; }
}

__global__ void count_deg_kernel(const int* __restrict__ col, int e) {
    int i = blockIdx.x * blockDim.x + threadIdx.x;
    if (i < e) atomicAdd(&g_deg[col[i]], 1);
}

__device__ __forceinline__ int block_excl_scan(int val, int* total) {
    __shared__ int wsum[32];
    int lane = threadIdx.x & 31, wid = threadIdx.x >> 5;
    int v = val;
#pragma unroll
    for (int o = 1; o < 32; o <<= 1) {
        int t = __shfl_up_sync(0xffffffffu, v, o);
        if (lane >= o) v += t;
    }
    if (lane == 31) wsum[wid] = v;
    __syncthreads();
    if (wid == 0) {
        int w = (lane < (blockDim.x >> 5)) ? wsum[lane] : 0;
#pragma unroll
        for (int o = 1; o < 32; o <<= 1) {
            int t = __shfl_up_sync(0xffffffffu, w, o);
            if (lane >= o) w += t;
        }
        wsum[lane] = w;
    }
    __syncthreads();
    int excl = v - val + (wid > 0 ? wsum[wid - 1] : 0);
    *total = wsum[(blockDim.x >> 5) - 1];
    return excl;
}

__global__ void scan1_kernel(int n) {
    int i = blockIdx.x * SCAN_B + threadIdx.x;
    int v = (i < n) ? g_deg[i] : 0;
    if (i < n) g_dinv[i] = rsqrtf((float)(v + 1));  // +1 self-loop
    int total;
    int excl = block_excl_scan(v, &total);
    if (i <= n) g_rowptr[i] = excl;
    if (threadIdx.x == 0) g_bsum[blockIdx.x] = total;
}

__global__ void scan2_kernel(int nb) {
    int v = (threadIdx.x < nb) ? g_bsum[threadIdx.x] : 0;
    int total;
    int excl = block_excl_scan(v, &total);
    if (threadIdx.x < nb) g_boff[threadIdx.x] = excl;
    if (threadIdx.x == 0) g_boff[nb] = total;
}

__global__ void scan3_kernel(int n, int nb) {
    int i = blockIdx.x * SCAN_B + threadIdx.x;
    if (i < n) g_rowptr[i] += g_boff[blockIdx.x];
    if (i == 0) g_rowptr[n] = g_boff[nb];
}

__global__ void fill_csr_kernel(const int* __restrict__ row,
                                const int* __restrict__ col, int e) {
    int i = blockIdx.x * blockDim.x + threadIdx.x;
    if (i < e) {
        int c = col[i];
        int p = g_rowptr[c] + atomicAdd(&g_fill[c], 1);
        g_csr_src[p] = row[i];
    }
}

// ---------------- tf32 hi/lo split helpers ----------------

__device__ __forceinline__ uint32_t f2tf32(float x) {
    uint32_t u;
    asm("cvt.rna.tf32.f32 %0, %1;" : "=r"(u) : "f"(x));
    return u;
}

__device__ __forceinline__ float2 split_pair(float v) {
    float hi = __uint_as_float(f2tf32(v));
    float lo = __uint_as_float(f2tf32(v - hi));
    return make_float2(hi, lo);
}

// x (fp32) -> g_x2 pairs (layer-0 input)
__global__ void convert_x2_kernel(const float* __restrict__ x, int total) {
    int i = blockIdx.x * blockDim.x + threadIdx.x;
    if (i < total) g_x2[i] = split_pair(x[i]);
}

// W (fp32, all layers) -> g_w2 pairs
__global__ void convert_w2_kernel(const float* __restrict__ W, int total) {
    int i = blockIdx.x * blockDim.x + threadIdx.x;
    if (i < total) g_w2[i] = split_pair(W[i]);
}

// ---------------- GEMM v5: h' = (X @ W) * dinv[row], 3xTF32 mma ----------------
// Block 512 thr (16 warps = 8m x 2n), tile M=128 N=128 K=128, warp tile 16x64.
// A: pre-split (hi,lo) pairs LDG.64 direct from global (L2-resident), 2-step pipeline.
// B: pre-split W2 staged to smem (raw copy), LDS.64 pairs in mainloop.
// D += Ahi*Bhi + Ahi*Blo + Alo*Bhi.

#define WSTR 264
#define GEMM_SMEM (128 * WSTR * 4)  // 135168 B

__device__ __forceinline__ void mma_tf32(float* c, const uint32_t* a,
                                         uint32_t b0, uint32_t b1) {
    asm volatile(
        "mma.sync.aligned.m16n8k8.row.col.f32.tf32.tf32.f32 "
        "{%0,%1,%2,%3}, {%4,%5,%6,%7}, {%8,%9}, {%0,%1,%2,%3};"
        : "+f"(c[0]), "+f"(c[1]), "+f"(c[2]), "+f"(c[3])
        : "r"(a[0]), "r"(a[1]), "r"(a[2]), "r"(a[3]), "r"(b0), "r"(b1));
}

__global__ __launch_bounds__(512, 1)
void gemm_mma(const float2* __restrict__ W2, int n) {
    extern __shared__ float smem[];
    float* sW = smem;  // [128 k][264 floats] = (hi,lo) pairs for 128 n

    // stage pre-split W2: raw copy, no math
    for (int i = threadIdx.x; i < 128 * 64; i += 512) {
        int k = i >> 6, j = i & 63;
        float4 v = ((const float4*)W2)[k * 64 + j];
        *(float4*)(sW + k * WSTR + j * 4) = v;
    }
    __syncthreads();

    int lane = threadIdx.x & 31;
    int w    = threadIdx.x >> 5;
    int wm   = w & 7;   // 8 m-slabs of 16 rows
    int wn   = w >> 3;  // 2 n-halves of 64 cols
    int g    = lane >> 2;
    int q    = lane & 3;

    int rowBase = blockIdx.x * 128;
    int r0 = rowBase + wm * 16 + g;
    int r1 = r0 + 8;
    // clamp OOB rows (their results are discarded in the epilogue)
    const float2* A0 = g_x2 + (size_t)min(r0, n - 1) * DD;
    const float2* A1 = g_x2 + (size_t)min(r1, n - 1) * DD;

    float c[8][4];
#pragma unroll
    for (int nt = 0; nt < 8; ++nt)
#pragma unroll
        for (int j = 0; j < 4; ++j) c[nt][j] = 0.f;

    float2 A[2][4];
#define LOADA(s, ks) do { int kk = (ks) * 8 + q;            \
        A[s][0] = __ldg(A0 + kk);     A[s][1] = __ldg(A1 + kk); \
        A[s][2] = __ldg(A0 + kk + 4); A[s][3] = __ldg(A1 + kk + 4); } while (0)

    LOADA(0, 0);
    LOADA(1, 1);

#pragma unroll
    for (int ks = 0; ks < 16; ++ks) {
        int cur = ks & 1;
        uint32_t ah[4], al[4];
#pragma unroll
        for (int j = 0; j < 4; ++j) {
            ah[j] = __float_as_uint(A[cur][j].x);
            al[j] = __float_as_uint(A[cur][j].y);
        }
        if (ks + 2 < 16) LOADA(cur, ks + 2);  // refill slot 2 steps ahead

        int k0 = ks * 8;
#pragma unroll
        for (int nt = 0; nt < 8; ++nt) {
            int ncol = wn * 64 + nt * 8 + g;
            float2 p0 = *(float2*)(sW + (size_t)(k0 + q) * WSTR + ncol * 2);
            float2 p1 = *(float2*)(sW + (size_t)(k0 + q + 4) * WSTR + ncol * 2);
            uint32_t bh0 = __float_as_uint(p0.x), bl0 = __float_as_uint(p0.y);
            uint32_t bh1 = __float_as_uint(p1.x), bl1 = __float_as_uint(p1.y);
            mma_tf32(c[nt], ah, bh0, bh1);
            mma_tf32(c[nt], ah, bl0, bl1);
            mma_tf32(c[nt], al, bh0, bh1);
        }
    }
#undef LOADA

    // epilogue: scale by dinv[row], store float2 pairs to g_h
    float d0 = (r0 < n) ? g_dinv[r0] : 0.f;
    float d1 = (r1 < n) ? g_dinv[r1] : 0.f;
#pragma unroll
    for (int nt = 0; nt < 8; ++nt) {
        int col = wn * 64 + nt * 8 + 2 * q;
        if (r0 < n)
            *(float2*)(g_h + (size_t)r0 * DD + col) =
                make_float2(c[nt][0] * d0, c[nt][1] * d0);
        if (r1 < n)
            *(float2*)(g_h + (size_t)r1 * DD + col) =
                make_float2(c[nt][2] * d1, c[nt][3] * d1);
    }
}

// ---------------- Aggregation: gather, no atomics ----------------
// result = relu(dinv[c]*(h'[c] + sum_p h'[src]) + bias)
// If last layer: write fp32 to out. Else: write (hi,lo) pairs to g_x2.
__global__ void aggregate_kernel(const float* __restrict__ bias,
                                 float* __restrict__ out, int writePairs, int n) {
    int node = (blockIdx.x * blockDim.x + threadIdx.x) >> 5;
    int lane = threadIdx.x & 31;
    if (node >= n) return;

    const float4* H = (const float4*)g_h;
    float4 acc = __ldg(&H[(size_t)node * 32 + lane]);  // self-loop h'

    int p   = g_rowptr[node];
    int end = g_rowptr[node + 1];
    for (; p + 4 <= end; p += 4) {
        int s0 = __ldg(&g_csr_src[p + 0]);
        int s1 = __ldg(&g_csr_src[p + 1]);
        int s2 = __ldg(&g_csr_src[p + 2]);
        int s3 = __ldg(&g_csr_src[p + 3]);
        float4 v0 = __ldg(&H[(size_t)s0 * 32 + lane]);
        float4 v1 = __ldg(&H[(size_t)s1 * 32 + lane]);
        float4 v2 = __ldg(&H[(size_t)s2 * 32 + lane]);
        float4 v3 = __ldg(&H[(size_t)s3 * 32 + lane]);
        acc.x += (v0.x + v1.x) + (v2.x + v3.x);
        acc.y += (v0.y + v1.y) + (v2.y + v3.y);
        acc.z += (v0.z + v1.z) + (v2.z + v3.z);
        acc.w += (v0.w + v1.w) + (v2.w + v3.w);
    }
    for (; p < end; ++p) {
        int s = __ldg(&g_csr_src[p]);
        float4 v = __ldg(&H[(size_t)s * 32 + lane]);
        acc.x += v.x; acc.y += v.y; acc.z += v.z; acc.w += v.w;
    }

    float di  = g_dinv[node];
    float4 bb = __ldg(&((const float4*)bias)[lane]);
    float4 o;
    o.x = fmaxf(acc.x * di + bb.x, 0.f);
    o.y = fmaxf(acc.y * di + bb.y, 0.f);
    o.z = fmaxf(acc.z * di + bb.z, 0.f);
    o.w = fmaxf(acc.w * di + bb.w, 0.f);

    if (writePairs) {
        float2* dst = g_x2 + (size_t)node * DD + lane * 4;
        dst[0] = split_pair(o.x);
        dst[1] = split_pair(o.y);
        dst[2] = split_pair(o.z);
        dst[3] = split_pair(o.w);
    } else {
        ((float4*)out)[(size_t)node * 32 + lane] = o;
    }
}

extern "C" void kernel_launch(void* const* d_in, const int* in_sizes, int n_in,
                              void* d_out, int out_size) {
    const float* x  = (const float*)d_in[0];
    const int*   ei = (const int*)d_in[1];
    const float* W  = (const float*)d_in[4];
    const float* b  = (const float*)d_in[5];
    float* out = (float*)d_out;

    int n = in_sizes[0] / DD;      // 50000
    int e = in_sizes[1] / 2;       // 800000
    const int* rowp = ei;          // sources
    const int* colp = ei + e;      // destinations
    int nb = (n + SCAN_B - 1) / SCAN_B;

    cudaFuncSetAttribute(gemm_mma,
                         cudaFuncAttributeMaxDynamicSharedMemorySize, GEMM_SMEM);

    float2* w2p = nullptr;
    cudaGetSymbolAddress((void**)&w2p, g_w2);

    int gemmGrid = (n + 127) / 128;

    // Preprocess + conversions; layer-0 GEMM only needs dinv (scan1) and x2,
    // so the CSR build continues behind it.
    zero_counters_kernel<<<(n + 255) / 256, 256>>>(n);
    count_deg_kernel<<<(e + 255) / 256, 256>>>(colp, e);
    scan1_kernel<<<nb, SCAN_B>>>(n);
    convert_w2_kernel<<<(LL * DD * DD + 255) / 256, 256>>>(W, LL * DD * DD);
    convert_x2_kernel<<<(n * DD + 255) / 256, 256>>>(x, n * DD);
    gemm_mma<<<gemmGrid, 512, GEMM_SMEM>>>(w2p, n);             // layer 0 GEMM
    scan2_kernel<<<1, SCAN_B>>>(nb);
    scan3_kernel<<<nb, SCAN_B>>>(n, nb);
    fill_csr_kernel<<<(e + 255) / 256, 256>>>(rowp, colp, e);
    aggregate_kernel<<<(n * 32 + 255) / 256, 256>>>(b, out, 1, n);  // layer 0 agg

    for (int l = 1; l < LL; ++l) {
        gemm_mma<<<gemmGrid, 512, GEMM_SMEM>>>(w2p + (size_t)l * DD * DD, n);
        aggregate_kernel<<<(n * 32 + 255) / 256, 256>>>(
            b + (size_t)l * DD, out, (l == LL - 1) ? 0 : 1, n);
    }
}

// round 8
// speedup vs baseline: 1.3891x; 1.3891x over previous
#include <cuda_runtime.h>
#include <cuda_bf16.h>
#include <cstdint>

#define MAXN 50000
#define DD 128
#define MAXE 800000
#define LL 4
#define SCAN_B 1024

// Scratch (no allocations allowed)
__device__ int    g_deg[MAXN];
__device__ int    g_fill[MAXN];
__device__ int    g_rowptr[MAXN + 1];
__device__ int    g_bsum[64];
__device__ int    g_boff[64];
__device__ int    g_csr_src[MAXE];
__device__ float  g_dinv[MAXN];
__device__ float  g_h[(size_t)MAXN * DD];    // h' = (X@W)*dinv[row]
__device__ float  g_buf[(size_t)MAXN * DD];  // layer output ping buffer

// ---------------- preprocessing ----------------

__global__ void zero_counters_kernel(int n) {
    int i = blockIdx.x * blockDim.x + threadIdx.x;
    if (i < n) { g_deg[i] = 0; g_fill[i] = 0; }
}

__global__ void count_deg_kernel(const int* __restrict__ col, int e) {
    int i = blockIdx.x * blockDim.x + threadIdx.x;
    if (i < e) atomicAdd(&g_deg[col[i]], 1);
}

__device__ __forceinline__ int block_excl_scan(int val, int* total) {
    __shared__ int wsum[32];
    int lane = threadIdx.x & 31, wid = threadIdx.x >> 5;
    int v = val;
#pragma unroll
    for (int o = 1; o < 32; o <<= 1) {
        int t = __shfl_up_sync(0xffffffffu, v, o);
        if (lane >= o) v += t;
    }
    if (lane == 31) wsum[wid] = v;
    __syncthreads();
    if (wid == 0) {
        int w = (lane < (blockDim.x >> 5)) ? wsum[lane] : 0;
#pragma unroll
        for (int o = 1; o < 32; o <<= 1) {
            int t = __shfl_up_sync(0xffffffffu, w, o);
            if (lane >= o) w += t;
        }
        wsum[lane] = w;
    }
    __syncthreads();
    int excl = v - val + (wid > 0 ? wsum[wid - 1] : 0);
    *total = wsum[(blockDim.x >> 5) - 1];
    return excl;
}

__global__ void scan1_kernel(int n) {
    int i = blockIdx.x * SCAN_B + threadIdx.x;
    int v = (i < n) ? g_deg[i] : 0;
    if (i < n) g_dinv[i] = rsqrtf((float)(v + 1));  // +1 self-loop
    int total;
    int excl = block_excl_scan(v, &total);
    if (i <= n) g_rowptr[i] = excl;
    if (threadIdx.x == 0) g_bsum[blockIdx.x] = total;
}

__global__ void scan2_kernel(int nb) {
    int v = (threadIdx.x < nb) ? g_bsum[threadIdx.x] : 0;
    int total;
    int excl = block_excl_scan(v, &total);
    if (threadIdx.x < nb) g_boff[threadIdx.x] = excl;
    if (threadIdx.x == 0) g_boff[nb] = total;
}

__global__ void scan3_kernel(int n, int nb) {
    int i = blockIdx.x * SCAN_B + threadIdx.x;
    if (i < n) g_rowptr[i] += g_boff[blockIdx.x];
    if (i == 0) g_rowptr[n] = g_boff[nb];
}

__global__ void fill_csr_kernel(const int* __restrict__ row,
                                const int* __restrict__ col, int e) {
    int i = blockIdx.x * blockDim.x + threadIdx.x;
    if (i < e) {
        int c = col[i];
        int p = g_rowptr[c] + atomicAdd(&g_fill[c], 1);
        g_csr_src[p] = row[i];
    }
}

// ---------------- GEMM v6: h' = (X @ W) * dinv[row], bf16x2 mma ----------------
// Block 1024 thr (32 warps = 8m x 4n), tile M=128 N=128 K=128, warp tile 16x32.
// fp32 split into (hi,lo) bf16 planes at staging. Three m16n8k16 passes:
// D += Ahi*Bhi + Ahi*Blo + Alo*Bhi  (error ~2^-16, well under 1e-3 gate).
// smem planes [128][68] uint32 words (each word = bf16x2 over consecutive k).

#define PSTR 68                      // words per row (64 data + 4 pad)
#define PLANE (128 * PSTR)           // words per plane
#define GEMM_SMEM (4 * PLANE * 4)    // 139264 B

__device__ __forceinline__ void mma_bf16(float* c, const uint32_t* a,
                                         uint32_t b0, uint32_t b1) {
    asm volatile(
        "mma.sync.aligned.m16n8k16.row.col.f32.bf16.bf16.f32 "
        "{%0,%1,%2,%3}, {%4,%5,%6,%7}, {%8,%9}, {%0,%1,%2,%3};"
        : "+f"(c[0]), "+f"(c[1]), "+f"(c[2]), "+f"(c[3])
        : "r"(a[0]), "r"(a[1]), "r"(a[2]), "r"(a[3]), "r"(b0), "r"(b1));
}

__device__ __forceinline__ uint32_t pack_hi(float x, float y) {
    __nv_bfloat162 h = make_bfloat162(__float2bfloat16(x), __float2bfloat16(y));
    return *(uint32_t*)&h;
}

__global__ __launch_bounds__(1024, 1)
void gemm_mma(const float* __restrict__ X, const float* __restrict__ W, int n) {
    extern __shared__ uint32_t smem[];
    uint32_t* sAhi = smem;
    uint32_t* sAlo = smem + PLANE;
    uint32_t* sBhi = smem + 2 * PLANE;
    uint32_t* sBlo = smem + 3 * PLANE;

    int tid = threadIdx.x;
    int rowBase = blockIdx.x * 128;

    // stage A = X tile: read float2 (k,k+1), split hi/lo, pack bf16x2
    for (int i = tid; i < 128 * 64; i += 1024) {
        int r = i >> 6, k2 = i & 63;
        float2 v = make_float2(0.f, 0.f);
        if (rowBase + r < n)
            v = ((const float2*)X)[(size_t)(rowBase + r) * 64 + k2];
        float hx = __bfloat162float(__float2bfloat16(v.x));
        float hy = __bfloat162float(__float2bfloat16(v.y));
        sAhi[r * PSTR + k2] = pack_hi(v.x, v.y);
        sAlo[r * PSTR + k2] = pack_hi(v.x - hx, v.y - hy);
    }
    // stage B[n][k] = W[k][n]: read W rows 2k2, 2k2+1 at col nn (coalesced over nn)
    for (int i = tid; i < 128 * 64; i += 1024) {
        int k2 = i >> 7, nn = i & 127;
        float v0 = W[(size_t)(2 * k2) * DD + nn];
        float v1 = W[(size_t)(2 * k2 + 1) * DD + nn];
        float h0 = __bfloat162float(__float2bfloat16(v0));
        float h1 = __bfloat162float(__float2bfloat16(v1));
        sBhi[nn * PSTR + k2] = pack_hi(v0, v1);
        sBlo[nn * PSTR + k2] = pack_hi(v0 - h0, v1 - h1);
    }
    __syncthreads();

    int lane = tid & 31;
    int w    = tid >> 5;
    int wm   = w & 7;   // 8 m-slabs of 16 rows
    int wn   = w >> 3;  // 4 n-quarters of 32 cols
    int g    = lane >> 2;
    int q    = lane & 3;

    float c[4][4];
#pragma unroll
    for (int nt = 0; nt < 4; ++nt)
#pragma unroll
        for (int j = 0; j < 4; ++j) c[nt][j] = 0.f;

    int m0 = wm * 16 + g;
    const uint32_t* a0hi = sAhi + m0 * PSTR;
    const uint32_t* a1hi = sAhi + (m0 + 8) * PSTR;
    const uint32_t* a0lo = sAlo + m0 * PSTR;
    const uint32_t* a1lo = sAlo + (m0 + 8) * PSTR;

#pragma unroll
    for (int ks = 0; ks < 8; ++ks) {
        int kw = ks * 8 + q;  // word index within row (1 word = 2 k)

        uint32_t ahi[4], alo[4];
        ahi[0] = a0hi[kw];     ahi[1] = a1hi[kw];
        ahi[2] = a0hi[kw + 4]; ahi[3] = a1hi[kw + 4];
        alo[0] = a0lo[kw];     alo[1] = a1lo[kw];
        alo[2] = a0lo[kw + 4]; alo[3] = a1lo[kw + 4];

#pragma unroll
        for (int nt = 0; nt < 4; ++nt) {
            int ncol = wn * 32 + nt * 8 + g;
            uint32_t bh0 = sBhi[ncol * PSTR + kw];
            uint32_t bh1 = sBhi[ncol * PSTR + kw + 4];
            uint32_t bl0 = sBlo[ncol * PSTR + kw];
            uint32_t bl1 = sBlo[ncol * PSTR + kw + 4];
            mma_bf16(c[nt], ahi, bh0, bh1);
            mma_bf16(c[nt], ahi, bl0, bl1);
            mma_bf16(c[nt], alo, bh0, bh1);
        }
    }

    // epilogue: scale by dinv[row], store float2 pairs
    int r0 = rowBase + m0;
    int r1 = r0 + 8;
    float d0 = (r0 < n) ? g_dinv[r0] : 0.f;
    float d1 = (r1 < n) ? g_dinv[r1] : 0.f;
#pragma unroll
    for (int nt = 0; nt < 4; ++nt) {
        int col = wn * 32 + nt * 8 + 2 * q;
        if (r0 < n)
            *(float2*)(g_h + (size_t)r0 * DD + col) =
                make_float2(c[nt][0] * d0, c[nt][1] * d0);
        if (r1 < n)
            *(float2*)(g_h + (size_t)r1 * DD + col) =
                make_float2(c[nt][2] * d1, c[nt][3] * d1);
    }
}

// ---------------- Aggregation: gather, no atomics ----------------
__global__ void aggregate_kernel(const float* __restrict__ bias,
                                 float* __restrict__ out, int n) {
    int node = (blockIdx.x * blockDim.x + threadIdx.x) >> 5;
    int lane = threadIdx.x & 31;
    if (node >= n) return;

    const float4* H = (const float4*)g_h;
    float4 acc = __ldg(&H[(size_t)node * 32 + lane]);  // self-loop h'

    int p   = g_rowptr[node];
    int end = g_rowptr[node + 1];
    for (; p + 4 <= end; p += 4) {
        int s0 = __ldg(&g_csr_src[p + 0]);
        int s1 = __ldg(&g_csr_src[p + 1]);
        int s2 = __ldg(&g_csr_src[p + 2]);
        int s3 = __ldg(&g_csr_src[p + 3]);
        float4 v0 = __ldg(&H[(size_t)s0 * 32 + lane]);
        float4 v1 = __ldg(&H[(size_t)s1 * 32 + lane]);
        float4 v2 = __ldg(&H[(size_t)s2 * 32 + lane]);
        float4 v3 = __ldg(&H[(size_t)s3 * 32 + lane]);
        acc.x += (v0.x + v1.x) + (v2.x + v3.x);
        acc.y += (v0.y + v1.y) + (v2.y + v3.y);
        acc.z += (v0.z + v1.z) + (v2.z + v3.z);
        acc.w += (v0.w + v1.w) + (v2.w + v3.w);
    }
    for (; p < end; ++p) {
        int s = __ldg(&g_csr_src[p]);
        float4 v = __ldg(&H[(size_t)s * 32 + lane]);
        acc.x += v.x; acc.y += v.y; acc.z += v.z; acc.w += v.w;
    }

    float di  = g_dinv[node];
    float4 bb = __ldg(&((const float4*)bias)[lane]);
    float4 o;
    o.x = fmaxf(acc.x * di + bb.x, 0.f);
    o.y = fmaxf(acc.y * di + bb.y, 0.f);
    o.z = fmaxf(acc.z * di + bb.z, 0.f);
    o.w = fmaxf(acc.w * di + bb.w, 0.f);
    ((float4*)out)[(size_t)node * 32 + lane] = o;
}

extern "C" void kernel_launch(void* const* d_in, const int* in_sizes, int n_in,
                              void* d_out, int out_size) {
    const float* x  = (const float*)d_in[0];
    const int*   ei = (const int*)d_in[1];
    const float* W  = (const float*)d_in[4];
    const float* b  = (const float*)d_in[5];
    float* out = (float*)d_out;

    int n = in_sizes[0] / DD;      // 50000
    int e = in_sizes[1] / 2;       // 800000
    const int* rowp = ei;          // sources
    const int* colp = ei + e;      // destinations
    int nb = (n + SCAN_B - 1) / SCAN_B;

    cudaFuncSetAttribute(gemm_mma,
                         cudaFuncAttributeMaxDynamicSharedMemorySize, GEMM_SMEM);

    float* bufp = nullptr;
    cudaGetSymbolAddress((void**)&bufp, g_buf);

    int gemmGrid = (n + 127) / 128;

    // Preprocess; layer-0 GEMM only needs dinv (scan1), so the CSR build
    // continues behind it.
    zero_counters_kernel<<<(n + 255) / 256, 256>>>(n);
    count_deg_kernel<<<(e + 255) / 256, 256>>>(colp, e);
    scan1_kernel<<<nb, SCAN_B>>>(n);
    gemm_mma<<<gemmGrid, 1024, GEMM_SMEM>>>(x, W, n);           // layer 0 GEMM
    scan2_kernel<<<1, SCAN_B>>>(nb);
    scan3_kernel<<<nb, SCAN_B>>>(n, nb);
    fill_csr_kernel<<<(e + 255) / 256, 256>>>(rowp, colp, e);
    aggregate_kernel<<<(n * 32 + 255) / 256, 256>>>(b, bufp, n);  // layer 0 agg

    const float* X = bufp;
    for (int l = 1; l < LL; ++l) {
        gemm_mma<<<gemmGrid, 1024, GEMM_SMEM>>>(X, W + (size_t)l * DD * DD, n);
        aggregate_kernel<<<(n * 32 + 255) / 256, 256>>>(
            b + (size_t)l * DD, (l == LL - 1) ? out : bufp, n);
        X = bufp;
    }
}

// round 9
// speedup vs baseline: 1.4405x; 1.0370x over previous
#include <cuda_runtime.h>
#include <cuda_bf16.h>
#include <cstdint>

#define MAXN 50000
#define DD 128
#define MAXE 800000
#define LL 4
#define SCAN_B 1024

// Scratch (no allocations allowed)
__device__ int    g_deg[MAXN];
__device__ int    g_fill[MAXN];
__device__ int    g_rowptr[MAXN + 1];
__device__ int    g_bsum[64];
__device__ int    g_boff[64];
__device__ int    g_csr_src[MAXE];
__device__ float  g_dinv[MAXN];
__device__ float  g_h[(size_t)MAXN * DD];    // h' = (X@W)*dinv[row]
__device__ float  g_buf[(size_t)MAXN * DD];  // layer output ping buffer

// ---------------- preprocessing ----------------

__global__ void zero_counters_kernel(int n) {
    int i = blockIdx.x * blockDim.x + threadIdx.x;
    if (i < n) { g_deg[i] = 0; g_fill[i] = 0; }
}

__global__ void count_deg_kernel(const int* __restrict__ col, int e) {
    int i = blockIdx.x * blockDim.x + threadIdx.x;
    if (i < e) atomicAdd(&g_deg[col[i]], 1);
}

__device__ __forceinline__ int block_excl_scan(int val, int* total) {
    __shared__ int wsum[32];
    int lane = threadIdx.x & 31, wid = threadIdx.x >> 5;
    int v = val;
#pragma unroll
    for (int o = 1; o < 32; o <<= 1) {
        int t = __shfl_up_sync(0xffffffffu, v, o);
        if (lane >= o) v += t;
    }
    if (lane == 31) wsum[wid] = v;
    __syncthreads();
    if (wid == 0) {
        int w = (lane < (blockDim.x >> 5)) ? wsum[lane] : 0;
#pragma unroll
        for (int o = 1; o < 32; o <<= 1) {
            int t = __shfl_up_sync(0xffffffffu, w, o);
            if (lane >= o) w += t;
        }
        wsum[lane] = w;
    }
    __syncthreads();
    int excl = v - val + (wid > 0 ? wsum[wid - 1] : 0);
    *total = wsum[(blockDim.x >> 5) - 1];
    return excl;
}

__global__ void scan1_kernel(int n) {
    int i = blockIdx.x * SCAN_B + threadIdx.x;
    int v = (i < n) ? g_deg[i] : 0;
    if (i < n) g_dinv[i] = rsqrtf((float)(v + 1));  // +1 self-loop
    int total;
    int excl = block_excl_scan(v, &total);
    if (i <= n) g_rowptr[i] = excl;
    if (threadIdx.x == 0) g_bsum[blockIdx.x] = total;
}

__global__ void scan2_kernel(int nb) {
    int v = (threadIdx.x < nb) ? g_bsum[threadIdx.x] : 0;
    int total;
    int excl = block_excl_scan(v, &total);
    if (threadIdx.x < nb) g_boff[threadIdx.x] = excl;
    if (threadIdx.x == 0) g_boff[nb] = total;
}

__global__ void scan3_kernel(int n, int nb) {
    int i = blockIdx.x * SCAN_B + threadIdx.x;
    if (i < n) g_rowptr[i] += g_boff[blockIdx.x];
    if (i == 0) g_rowptr[n] = g_boff[nb];
}

__global__ void fill_csr_kernel(const int* __restrict__ row,
                                const int* __restrict__ col, int e) {
    int i = blockIdx.x * blockDim.x + threadIdx.x;
    if (i < e) {
        int c = col[i];
        int p = g_rowptr[c] + atomicAdd(&g_fill[c], 1);
        g_csr_src[p] = row[i];
    }
}

// ---------------- GEMM v7: persistent bf16x2 mma ----------------
// Grid = #SMs, block 1024 thr (32 warps = 8m x 4n). Each block stages the
// (hi,lo) bf16 W planes ONCE, then loops over M-tiles (128 rows) stride grid.
// Per tile: stage A planes, mainloop m16n8k16 x3 passes, epilogue *dinv.
// Layouts (words): A planes [128 rows][68]; B planes [64 kw][132 ncol]
//   A loads/stores and B loads/stores all bank-conflict-free.

#define A_STR 68
#define B_STR 132
#define A_PLANE (128 * A_STR)          // 8704 words
#define B_PLANE (64 * B_STR)           // 8448 words
#define GEMM_SMEM ((2 * A_PLANE + 2 * B_PLANE) * 4)  // 137216 B

__device__ __forceinline__ void mma_bf16(float* c, const uint32_t* a,
                                         uint32_t b0, uint32_t b1) {
    asm volatile(
        "mma.sync.aligned.m16n8k16.row.col.f32.bf16.bf16.f32 "
        "{%0,%1,%2,%3}, {%4,%5,%6,%7}, {%8,%9}, {%0,%1,%2,%3};"
        : "+f"(c[0]), "+f"(c[1]), "+f"(c[2]), "+f"(c[3])
        : "r"(a[0]), "r"(a[1]), "r"(a[2]), "r"(a[3]), "r"(b0), "r"(b1));
}

__device__ __forceinline__ uint32_t pack2(float x, float y) {
    __nv_bfloat162 h = make_bfloat162(__float2bfloat16(x), __float2bfloat16(y));
    return *(uint32_t*)&h;
}

__global__ __launch_bounds__(1024, 1)
void gemm_mma(const float* __restrict__ X, const float* __restrict__ W,
              int n, int numTiles) {
    extern __shared__ uint32_t smem[];
    uint32_t* sAhi = smem;
    uint32_t* sAlo = smem + A_PLANE;
    uint32_t* sBhi = smem + 2 * A_PLANE;
    uint32_t* sBlo = smem + 2 * A_PLANE + B_PLANE;

    int tid  = threadIdx.x;
    int lane = tid & 31;
    int w    = tid >> 5;
    int wm   = w & 7;   // 8 m-slabs of 16 rows
    int wn   = w >> 3;  // 4 n-quarters of 32 cols
    int g    = lane >> 2;
    int q    = lane & 3;

    // ---- stage W once: B[kw][ncol], kw = k-word (2 k per word) ----
    for (int i = tid; i < 64 * 128; i += 1024) {
        int kw = i >> 7, nn = i & 127;
        float v0 = W[(size_t)(2 * kw) * DD + nn];
        float v1 = W[(size_t)(2 * kw + 1) * DD + nn];
        float h0 = __bfloat162float(__float2bfloat16(v0));
        float h1 = __bfloat162float(__float2bfloat16(v1));
        sBhi[kw * B_STR + nn] = pack2(v0, v1);
        sBlo[kw * B_STR + nn] = pack2(v0 - h0, v1 - h1);
    }

    for (int t = blockIdx.x; t < numTiles; t += gridDim.x) {
        int rowBase = t * 128;

        __syncthreads();  // previous mainloop done reading A planes

        // ---- stage A tile: global fp32 -> (hi,lo) bf16x2 planes ----
        for (int i = tid; i < 128 * 32; i += 1024) {
            int r = i >> 5, c4 = i & 31;
            float4 v = make_float4(0.f, 0.f, 0.f, 0.f);
            if (rowBase + r < n)
                v = ((const float4*)X)[(size_t)(rowBase + r) * 32 + c4];
            float hx = __bfloat162float(__float2bfloat16(v.x));
            float hy = __bfloat162float(__float2bfloat16(v.y));
            float hz = __bfloat162float(__float2bfloat16(v.z));
            float hw = __bfloat162float(__float2bfloat16(v.w));
            uint2 hi = make_uint2(pack2(v.x, v.y), pack2(v.z, v.w));
            uint2 lo = make_uint2(pack2(v.x - hx, v.y - hy),
                                  pack2(v.z - hz, v.w - hw));
            *(uint2*)&sAhi[r * A_STR + 2 * c4] = hi;
            *(uint2*)&sAlo[r * A_STR + 2 * c4] = lo;
        }
        __syncthreads();

        // ---- mainloop ----
        float c[4][4];
#pragma unroll
        for (int nt = 0; nt < 4; ++nt)
#pragma unroll
            for (int j = 0; j < 4; ++j) c[nt][j] = 0.f;

        int m0 = wm * 16 + g;
        const uint32_t* a0hi = sAhi + m0 * A_STR;
        const uint32_t* a1hi = sAhi + (m0 + 8) * A_STR;
        const uint32_t* a0lo = sAlo + m0 * A_STR;
        const uint32_t* a1lo = sAlo + (m0 + 8) * A_STR;

#pragma unroll
        for (int ks = 0; ks < 8; ++ks) {
            int kw = ks * 8 + q;

            uint32_t ahi[4], alo[4];
            ahi[0] = a0hi[kw];     ahi[1] = a1hi[kw];
            ahi[2] = a0hi[kw + 4]; ahi[3] = a1hi[kw + 4];
            alo[0] = a0lo[kw];     alo[1] = a1lo[kw];
            alo[2] = a0lo[kw + 4]; alo[3] = a1lo[kw + 4];

#pragma unroll
            for (int nt = 0; nt < 4; ++nt) {
                int ncol = wn * 32 + nt * 8 + g;
                uint32_t bh0 = sBhi[kw * B_STR + ncol];
                uint32_t bh1 = sBhi[(kw + 4) * B_STR + ncol];
                uint32_t bl0 = sBlo[kw * B_STR + ncol];
                uint32_t bl1 = sBlo[(kw + 4) * B_STR + ncol];
                mma_bf16(c[nt], ahi, bh0, bh1);
                mma_bf16(c[nt], ahi, bl0, bl1);
                mma_bf16(c[nt], alo, bh0, bh1);
            }
        }

        // ---- epilogue: scale by dinv[row], store float2 pairs ----
        int r0 = rowBase + m0;
        int r1 = r0 + 8;
        float d0 = (r0 < n) ? g_dinv[r0] : 0.f;
        float d1 = (r1 < n) ? g_dinv[r1] : 0.f;
#pragma unroll
        for (int nt = 0; nt < 4; ++nt) {
            int col = wn * 32 + nt * 8 + 2 * q;
            if (r0 < n)
                *(float2*)(g_h + (size_t)r0 * DD + col) =
                    make_float2(c[nt][0] * d0, c[nt][1] * d0);
            if (r1 < n)
                *(float2*)(g_h + (size_t)r1 * DD + col) =
                    make_float2(c[nt][2] * d1, c[nt][3] * d1);
        }
    }
}

// ---------------- Aggregation: gather, no atomics ----------------
__global__ void aggregate_kernel(const float* __restrict__ bias,
                                 float* __restrict__ out, int n) {
    int node = (blockIdx.x * blockDim.x + threadIdx.x) >> 5;
    int lane = threadIdx.x & 31;
    if (node >= n) return;

    const float4* H = (const float4*)g_h;
    float4 acc = __ldg(&H[(size_t)node * 32 + lane]);  // self-loop h'

    int p   = g_rowptr[node];
    int end = g_rowptr[node + 1];
    for (; p + 4 <= end; p += 4) {
        int s0 = __ldg(&g_csr_src[p + 0]);
        int s1 = __ldg(&g_csr_src[p + 1]);
        int s2 = __ldg(&g_csr_src[p + 2]);
        int s3 = __ldg(&g_csr_src[p + 3]);
        float4 v0 = __ldg(&H[(size_t)s0 * 32 + lane]);
        float4 v1 = __ldg(&H[(size_t)s1 * 32 + lane]);
        float4 v2 = __ldg(&H[(size_t)s2 * 32 + lane]);
        float4 v3 = __ldg(&H[(size_t)s3 * 32 + lane]);
        acc.x += (v0.x + v1.x) + (v2.x + v3.x);
        acc.y += (v0.y + v1.y) + (v2.y + v3.y);
        acc.z += (v0.z + v1.z) + (v2.z + v3.z);
        acc.w += (v0.w + v1.w) + (v2.w + v3.w);
    }
    for (; p < end; ++p) {
        int s = __ldg(&g_csr_src[p]);
        float4 v = __ldg(&H[(size_t)s * 32 + lane]);
        acc.x += v.x; acc.y += v.y; acc.z += v.z; acc.w += v.w;
    }

    float di  = g_dinv[node];
    float4 bb = __ldg(&((const float4*)bias)[lane]);
    float4 o;
    o.x = fmaxf(acc.x * di + bb.x, 0.f);
    o.y = fmaxf(acc.y * di + bb.y, 0.f);
    o.z = fmaxf(acc.z * di + bb.z, 0.f);
    o.w = fmaxf(acc.w * di + bb.w, 0.f);
    ((float4*)out)[(size_t)node * 32 + lane] = o;
}

extern "C" void kernel_launch(void* const* d_in, const int* in_sizes, int n_in,
                              void* d_out, int out_size) {
    const float* x  = (const float*)d_in[0];
    const int*   ei = (const int*)d_in[1];
    const float* W  = (const float*)d_in[4];
    const float* b  = (const float*)d_in[5];
    float* out = (float*)d_out;

    int n = in_sizes[0] / DD;      // 50000
    int e = in_sizes[1] / 2;       // 800000
    const int* rowp = ei;          // sources
    const int* colp = ei + e;      // destinations
    int nb = (n + SCAN_B - 1) / SCAN_B;
    int numTiles = (n + 127) / 128;

    int sms = 148;
    cudaDeviceGetAttribute(&sms, cudaDevAttrMultiProcessorCount, 0);
    int gemmGrid = numTiles < sms ? numTiles : sms;

    cudaFuncSetAttribute(gemm_mma,
                         cudaFuncAttributeMaxDynamicSharedMemorySize, GEMM_SMEM);

    float* bufp = nullptr;
    cudaGetSymbolAddress((void**)&bufp, g_buf);

    // Preprocess; layer-0 GEMM only needs dinv (scan1), so the CSR build
    // continues behind it.
    zero_counters_kernel<<<(n + 255) / 256, 256>>>(n);
    count_deg_kernel<<<(e + 255) / 256, 256>>>(colp, e);
    scan1_kernel<<<nb, SCAN_B>>>(n);
    gemm_mma<<<gemmGrid, 1024, GEMM_SMEM>>>(x, W, n, numTiles);  // layer 0
    scan2_kernel<<<1, SCAN_B>>>(nb);
    scan3_kernel<<<nb, SCAN_B>>>(n, nb);
    fill_csr_kernel<<<(e + 255) / 256, 256>>>(rowp, colp, e);
    aggregate_kernel<<<(n * 32 + 255) / 256, 256>>>(b, bufp, n);  // layer 0 agg

    const float* X = bufp;
    for (int l = 1; l < LL; ++l) {
        gemm_mma<<<gemmGrid, 1024, GEMM_SMEM>>>(X, W + (size_t)l * DD * DD, n,
                                                numTiles);
        aggregate_kernel<<<(n * 32 + 255) / 256, 256>>>(
            b + (size_t)l * DD, (l == LL - 1) ? out : bufp, n);
        X = bufp;
    }
}